// round 1
// baseline (speedup 1.0000x reference)
#include <cuda_runtime.h>
#include <math.h>

#define NPTS 512
#define DDIM 128
#define NMC  64
#define NROWS (3*NMC*NPTS)          // 98304 sample rows
#define DENOM 16777216.0            // NMC*NPTS*NPTS

// Scratch (static device globals — no allocation allowed)
__device__ float  g_X[(size_t)3*NMC*NPTS*DDIM];   // [set][m][n][d], 50.3MB
__device__ float  g_norm[3*NMC*NPTS];             // squared norms per row
__device__ double g_accum;

__global__ void k_zero() { g_accum = 0.0; }

// One warp per sample row: x = mu + sigma*eps, write X and ||x||^2.
__global__ void k_gen(const float* __restrict__ mu, const float* __restrict__ sigma,
                      const float* __restrict__ epsA, const float* __restrict__ epsB,
                      const float* __restrict__ epsC) {
    int w = (blockIdx.x * blockDim.x + threadIdx.x) >> 5;
    int lane = threadIdx.x & 31;
    if (w >= NROWS) return;
    int s   = w / (NMC*NPTS);
    int rem = w - s*(NMC*NPTS);
    int m   = rem / NPTS;
    int n   = rem - m*NPTS;
    const float* eps = (s == 0) ? epsA : (s == 1) ? epsB : epsC;
    const float4* mu4 = (const float4*)(mu    + (size_t)(s*NPTS + n)*DDIM);
    const float4* sg4 = (const float4*)(sigma + (size_t)(s*NPTS + n)*DDIM);
    const float4* ep4 = (const float4*)(eps   + ((size_t)m*NPTS + n)*DDIM);
    float4 a = mu4[lane], b = sg4[lane], e = ep4[lane];
    float4 x;
    x.x = fmaf(b.x, e.x, a.x);
    x.y = fmaf(b.y, e.y, a.y);
    x.z = fmaf(b.z, e.z, a.z);
    x.w = fmaf(b.w, e.w, a.w);
    ((float4*)(g_X + (size_t)w*DDIM))[lane] = x;
    float ss = x.x*x.x + x.y*x.y + x.z*x.z + x.w*x.w;
    #pragma unroll
    for (int o = 16; o; o >>= 1) ss += __shfl_xor_sync(0xffffffffu, ss, o);
    if (lane == 0) g_norm[w] = ss;
}

// Batched Gram GEMM + fused distance-loss epilogue.
// blockIdx.z encodes (m, pair): pair 0 = (A,C) pos, 1 = (B,A) neg, 2 = (B,C) neg.
#define BM 128
#define BN 128
#define BK 16

__global__ __launch_bounds__(256) void k_dist() {
    __shared__ __align__(16) float Xs[BK][BM + 4];
    __shared__ __align__(16) float Ys[BK][BN + 4];

    int p = blockIdx.z % 3;
    int m = blockIdx.z / 3;
    int rs = (p == 0) ? 0 : 1;
    int cs = (p == 0) ? 2 : ((p == 1) ? 0 : 2);

    const float* Xg = g_X + (size_t)(rs*NMC + m) * NPTS * DDIM;
    const float* Yg = g_X + (size_t)(cs*NMC + m) * NPTS * DDIM;
    const float* nX = g_norm + (size_t)(rs*NMC + m) * NPTS;
    const float* nY = g_norm + (size_t)(cs*NMC + m) * NPTS;

    int row0 = blockIdx.y * BM;
    int col0 = blockIdx.x * BN;

    int tid = threadIdx.x;
    int tx  = tid & 15;         // 0..15 -> 8 cols each
    int ty  = tid >> 4;         // 0..15 -> 8 rows each
    int lr  = tid >> 2;         // 0..63 load row
    int lk  = (tid & 3) * 4;    // 0,4,8,12 load k

    float acc[8][8];
    #pragma unroll
    for (int i = 0; i < 8; i++)
        #pragma unroll
        for (int j = 0; j < 8; j++) acc[i][j] = 0.0f;

    for (int k0 = 0; k0 < DDIM; k0 += BK) {
        #pragma unroll
        for (int rr = 0; rr < BM; rr += 64) {
            float4 v = *(const float4*)(Xg + (size_t)(row0 + lr + rr)*DDIM + k0 + lk);
            Xs[lk+0][lr+rr] = v.x; Xs[lk+1][lr+rr] = v.y;
            Xs[lk+2][lr+rr] = v.z; Xs[lk+3][lr+rr] = v.w;
            float4 u = *(const float4*)(Yg + (size_t)(col0 + lr + rr)*DDIM + k0 + lk);
            Ys[lk+0][lr+rr] = u.x; Ys[lk+1][lr+rr] = u.y;
            Ys[lk+2][lr+rr] = u.z; Ys[lk+3][lr+rr] = u.w;
        }
        __syncthreads();
        #pragma unroll
        for (int kk = 0; kk < BK; kk++) {
            float4 x0 = *(const float4*)&Xs[kk][ty*8];
            float4 x1 = *(const float4*)&Xs[kk][ty*8 + 4];
            float4 y0 = *(const float4*)&Ys[kk][tx*8];
            float4 y1 = *(const float4*)&Ys[kk][tx*8 + 4];
            float xr[8] = {x0.x,x0.y,x0.z,x0.w,x1.x,x1.y,x1.z,x1.w};
            float yr[8] = {y0.x,y0.y,y0.z,y0.w,y1.x,y1.y,y1.z,y1.w};
            #pragma unroll
            for (int i = 0; i < 8; i++)
                #pragma unroll
                for (int j = 0; j < 8; j++)
                    acc[i][j] = fmaf(xr[i], yr[j], acc[i][j]);
        }
        __syncthreads();
    }

    // Epilogue: d2 = ||x||^2 + ||y||^2 - 2 x.y, fused loss terms.
    float xn[8], yn[8];
    #pragma unroll
    for (int i = 0; i < 8; i++) xn[i] = nX[row0 + ty*8 + i];
    #pragma unroll
    for (int j = 0; j < 8; j++) yn[j] = nY[col0 + tx*8 + j];

    float local = 0.0f;
    if (p == 0) {
        #pragma unroll
        for (int i = 0; i < 8; i++)
            #pragma unroll
            for (int j = 0; j < 8; j++) {
                float d2 = xn[i] + yn[j] - 2.0f*acc[i][j];
                local += fmaxf(d2, 1e-12f);
            }
    } else {
        #pragma unroll
        for (int i = 0; i < 8; i++)
            #pragma unroll
            for (int j = 0; j < 8; j++) {
                float d2 = xn[i] + yn[j] - 2.0f*acc[i][j];
                if (d2 < 4.0f) {   // relu(2 - d) > 0 iff d2 < 4
                    float d = sqrtf(fmaxf(d2, 1e-12f));
                    float t = 2.0f - d;
                    local += t*t;
                }
            }
    }

    // Block reduction -> one double atomic per CTA
    #pragma unroll
    for (int o = 16; o; o >>= 1) local += __shfl_xor_sync(0xffffffffu, local, o);
    __shared__ float red[8];
    int warp = tid >> 5;
    if ((tid & 31) == 0) red[warp] = local;
    __syncthreads();
    if (warp == 0) {
        float v = (tid < 8) ? red[tid] : 0.0f;
        #pragma unroll
        for (int o = 4; o; o >>= 1) v += __shfl_xor_sync(0xffffffffu, v, o);
        if (tid == 0) atomicAdd(&g_accum, (double)v);
    }
}

__global__ void k_final(float* __restrict__ out) {
    out[0] = (float)(g_accum * (1.0 / DENOM));
}

extern "C" void kernel_launch(void* const* d_in, const int* in_sizes, int n_in,
                              void* d_out, int out_size) {
    const float* mu    = (const float*)d_in[0];
    const float* sigma = (const float*)d_in[1];
    const float* epsA  = (const float*)d_in[2];
    const float* epsB  = (const float*)d_in[3];
    const float* epsC  = (const float*)d_in[4];
    (void)in_sizes; (void)n_in; (void)out_size;

    k_zero<<<1, 1>>>();
    k_gen<<<(NROWS * 32) / 256, 256>>>(mu, sigma, epsA, epsB, epsC);
    dim3 grid(NPTS / BN, NPTS / BM, 3 * NMC);
    k_dist<<<grid, 256>>>();
    k_final<<<1, 1>>>((float*)d_out);
}

// round 3
// speedup vs baseline: 4.1488x; 4.1488x over previous
#include <cuda_runtime.h>
#include <cuda_bf16.h>
#include <math.h>
#include <stdint.h>

#define NPTS 512
#define DDIM 128
#define NMC  64
#define NROWS (3*NMC*NPTS)
#define DENOM 16777216.0

// Scratch (static device globals — no allocation allowed)
__device__ __nv_bfloat16 g_Xbf[(size_t)3*NMC*NPTS*DDIM];  // 25.2MB
__device__ float  g_norm[3*NMC*NPTS];
__device__ double g_accum;

__device__ __forceinline__ uint32_t smem_u32(const void* p) {
    uint32_t a;
    asm("{ .reg .u64 t; cvta.to.shared.u64 t, %1; cvt.u32.u64 %0, t; }" : "=r"(a) : "l"(p));
    return a;
}

__device__ __forceinline__ void ldmatrix_x4(uint32_t* r, uint32_t addr) {
    asm volatile("ldmatrix.sync.aligned.m8n8.x4.shared.b16 {%0,%1,%2,%3}, [%4];"
                 : "=r"(r[0]), "=r"(r[1]), "=r"(r[2]), "=r"(r[3]) : "r"(addr));
}

__device__ __forceinline__ void mma_bf16(float* c, const uint32_t* a, const uint32_t* b) {
    asm volatile(
        "mma.sync.aligned.m16n8k16.row.col.f32.bf16.bf16.f32 "
        "{%0,%1,%2,%3}, {%4,%5,%6,%7}, {%8,%9}, {%0,%1,%2,%3};"
        : "+f"(c[0]), "+f"(c[1]), "+f"(c[2]), "+f"(c[3])
        : "r"(a[0]), "r"(a[1]), "r"(a[2]), "r"(a[3]), "r"(b[0]), "r"(b[1]));
}

// ---------------- kernels ----------------
__global__ void k_zero() { g_accum = 0.0; }

// One warp per sample row: x = mu + sigma*eps -> bf16 X, fp32 ||x||^2.
__global__ void k_gen(const float* __restrict__ mu, const float* __restrict__ sigma,
                      const float* __restrict__ epsA, const float* __restrict__ epsB,
                      const float* __restrict__ epsC) {
    int w = (blockIdx.x * blockDim.x + threadIdx.x) >> 5;
    int lane = threadIdx.x & 31;
    if (w >= NROWS) return;
    int s   = w / (NMC*NPTS);
    int rem = w - s*(NMC*NPTS);
    int m   = rem / NPTS;
    int n   = rem - m*NPTS;
    const float* eps = (s == 0) ? epsA : (s == 1) ? epsB : epsC;
    float4 a = ((const float4*)(mu    + (size_t)(s*NPTS + n)*DDIM))[lane];
    float4 b = ((const float4*)(sigma + (size_t)(s*NPTS + n)*DDIM))[lane];
    float4 e = ((const float4*)(eps   + ((size_t)m*NPTS + n)*DDIM))[lane];
    float4 x;
    x.x = fmaf(b.x, e.x, a.x);
    x.y = fmaf(b.y, e.y, a.y);
    x.z = fmaf(b.z, e.z, a.z);
    x.w = fmaf(b.w, e.w, a.w);
    __nv_bfloat162 p0 = __floats2bfloat162_rn(x.x, x.y);
    __nv_bfloat162 p1 = __floats2bfloat162_rn(x.z, x.w);
    uint2 packed;
    packed.x = *(uint32_t*)&p0;
    packed.y = *(uint32_t*)&p1;
    ((uint2*)(g_Xbf + (size_t)w*DDIM))[lane] = packed;
    float ss = x.x*x.x + x.y*x.y + x.z*x.z + x.w*x.w;
    #pragma unroll
    for (int o = 16; o; o >>= 1) ss += __shfl_xor_sync(0xffffffffu, ss, o);
    if (lane == 0) g_norm[w] = ss;
}

// SMEM layout (dynamic):
//   [0:512)        xn[128]
//   [512:1024)     yn[128]
//   [1024:33792)   A tile (128 rows x 256B, XOR-swizzled 16B chunks)
//   [33792:66560)  B tile
#define SM_XN 0
#define SM_YN 512
#define SM_A  1024
#define SM_B  33792
#define SM_TOTAL 66560

// TN warp-MMA Gram GEMM + fused distance-loss epilogue.
// blockIdx.z = m*3 + pair; pair 0=(A,C) pos, 1=(B,A) neg, 2=(B,C) neg.
__global__ __launch_bounds__(256) void k_dist() {
    extern __shared__ char smem[];
    uint32_t sb = smem_u32(smem);
    int tid  = threadIdx.x;
    int lane = tid & 31;
    int w    = tid >> 5;
    int warp_m = w & 3;     // 4 warps over M (32 rows each)
    int warp_n = w >> 2;    // 2 warps over N (64 cols each)

    int p = blockIdx.z % 3;
    int m = blockIdx.z / 3;
    int rs = (p == 0) ? 0 : 1;
    int cs = (p == 0) ? 2 : ((p == 1) ? 0 : 2);

    const __nv_bfloat16* Xg = g_Xbf + (size_t)(rs*NMC + m) * NPTS * DDIM;
    const __nv_bfloat16* Yg = g_Xbf + (size_t)(cs*NMC + m) * NPTS * DDIM;
    const float* nX = g_norm + (size_t)(rs*NMC + m) * NPTS;
    const float* nY = g_norm + (size_t)(cs*NMC + m) * NPTS;
    int row0 = blockIdx.y * 128;
    int col0 = blockIdx.x * 128;

    // Load norms
    if (tid < 128) {
        ((float*)(smem + SM_XN))[tid] = nX[row0 + tid];
        ((float*)(smem + SM_YN))[tid] = nY[col0 + tid];
    }

    // Load A/B 128x128 bf16 tiles into swizzled SMEM (16B chunks, c' = c ^ (row&7))
    {
        const uint4* A16 = (const uint4*)(Xg + (size_t)row0 * DDIM);
        const uint4* B16 = (const uint4*)(Yg + (size_t)col0 * DDIM);
        #pragma unroll
        for (int it = 0; it < 8; it++) {
            int f   = it * 256 + tid;        // 2048 chunks total
            int row = f >> 4;
            int c   = f & 15;
            uint32_t dst = (uint32_t)(row * 256 + ((c ^ (row & 7)) << 4));
            *(uint4*)(smem + SM_A + dst) = A16[row * 16 + c];
            *(uint4*)(smem + SM_B + dst) = B16[row * 16 + c];
        }
    }
    __syncthreads();

    float acc[2][8][4];
    #pragma unroll
    for (int mt = 0; mt < 2; mt++)
        #pragma unroll
        for (int nt = 0; nt < 8; nt++)
            #pragma unroll
            for (int r = 0; r < 4; r++) acc[mt][nt][r] = 0.0f;

    // ldmatrix address helpers (element row, element k-col -> swizzled byte addr)
    // chunk = kcol/8 ; addr = base + row*256 + ((chunk ^ (row&7))<<4)
    #pragma unroll
    for (int ks = 0; ks < 8; ks++) {
        uint32_t a[2][4];
        #pragma unroll
        for (int mt = 0; mt < 2; mt++) {
            int r  = warp_m * 32 + mt * 16 + (lane & 15);
            int kc = ks * 16 + (lane >> 4) * 8;
            uint32_t addr = sb + SM_A + (uint32_t)(r * 256 + (((kc >> 3) ^ (r & 7)) << 4));
            ldmatrix_x4(a[mt], addr);
        }
        uint32_t b[8][2];
        #pragma unroll
        for (int nt2 = 0; nt2 < 4; nt2++) {
            // x4: mat0=(n0-7,k0-7) mat1=(n0-7,k8-15) mat2=(n8-15,k0-7) mat3=(n8-15,k8-15)
            int r  = warp_n * 64 + nt2 * 16 + (lane & 7) + ((lane >> 4) << 3);
            int kc = ks * 16 + ((lane >> 3) & 1) * 8;
            uint32_t addr = sb + SM_B + (uint32_t)(r * 256 + (((kc >> 3) ^ (r & 7)) << 4));
            uint32_t t[4];
            ldmatrix_x4(t, addr);
            b[nt2*2][0]   = t[0]; b[nt2*2][1]   = t[1];
            b[nt2*2+1][0] = t[2]; b[nt2*2+1][1] = t[3];
        }
        #pragma unroll
        for (int mt = 0; mt < 2; mt++)
            #pragma unroll
            for (int nt = 0; nt < 8; nt++)
                mma_bf16(acc[mt][nt], a[mt], b[nt]);
    }

    // Epilogue: fragment (mt,nt) reg r -> m = warp_m*32+mt*16+(lane/4)+(r>=2?8:0),
    //                                     n = warp_n*64+nt*8+(lane%4)*2+(r&1)
    const float* xns = (const float*)(smem + SM_XN);
    const float* yns = (const float*)(smem + SM_YN);
    float local = 0.0f;
    #pragma unroll
    for (int mt = 0; mt < 2; mt++) {
        int mbase = warp_m * 32 + mt * 16 + (lane >> 2);
        float xn0 = xns[mbase];
        float xn1 = xns[mbase + 8];
        #pragma unroll
        for (int nt = 0; nt < 8; nt++) {
            int nbase = warp_n * 64 + nt * 8 + (lane & 3) * 2;
            float yn0 = yns[nbase];
            float yn1 = yns[nbase + 1];
            float d2_00 = xn0 + yn0 - 2.0f * acc[mt][nt][0];
            float d2_01 = xn0 + yn1 - 2.0f * acc[mt][nt][1];
            float d2_10 = xn1 + yn0 - 2.0f * acc[mt][nt][2];
            float d2_11 = xn1 + yn1 - 2.0f * acc[mt][nt][3];
            if (p == 0) {
                local += fmaxf(d2_00, 1e-12f) + fmaxf(d2_01, 1e-12f)
                       + fmaxf(d2_10, 1e-12f) + fmaxf(d2_11, 1e-12f);
            } else {
                if (d2_00 < 4.0f) { float t = 2.0f - sqrtf(fmaxf(d2_00, 1e-12f)); local += t*t; }
                if (d2_01 < 4.0f) { float t = 2.0f - sqrtf(fmaxf(d2_01, 1e-12f)); local += t*t; }
                if (d2_10 < 4.0f) { float t = 2.0f - sqrtf(fmaxf(d2_10, 1e-12f)); local += t*t; }
                if (d2_11 < 4.0f) { float t = 2.0f - sqrtf(fmaxf(d2_11, 1e-12f)); local += t*t; }
            }
        }
    }

    // Reduce: warp -> block -> one double atomic
    #pragma unroll
    for (int o = 16; o; o >>= 1) local += __shfl_xor_sync(0xffffffffu, local, o);
    __shared__ float red[8];
    if (lane == 0) red[w] = local;
    __syncthreads();
    if (tid == 0) {
        float v = red[0] + red[1] + red[2] + red[3]
                + red[4] + red[5] + red[6] + red[7];
        atomicAdd(&g_accum, (double)v);
    }
}

__global__ void k_final(float* __restrict__ out) {
    out[0] = (float)(g_accum * (1.0 / DENOM));
}

extern "C" void kernel_launch(void* const* d_in, const int* in_sizes, int n_in,
                              void* d_out, int out_size) {
    const float* mu    = (const float*)d_in[0];
    const float* sigma = (const float*)d_in[1];
    const float* epsA  = (const float*)d_in[2];
    const float* epsB  = (const float*)d_in[3];
    const float* epsC  = (const float*)d_in[4];
    (void)in_sizes; (void)n_in; (void)out_size;

    cudaFuncSetAttribute(k_dist, cudaFuncAttributeMaxDynamicSharedMemorySize, SM_TOTAL);

    k_zero<<<1, 1>>>();
    k_gen<<<(NROWS * 32) / 256, 256>>>(mu, sigma, epsA, epsB, epsC);
    dim3 grid(4, 4, 3 * NMC);
    k_dist<<<grid, 256, SM_TOTAL>>>();
    k_final<<<1, 1>>>((float*)d_out);
}